// round 1
// baseline (speedup 1.0000x reference)
#include <cuda_runtime.h>
#include <cuda_bf16.h>
#include <cstdint>

// Problem constants
#define NE   8       // experts
#define NH   1024    // hidden
#define NM   2048    // intermediate
#define NTOK 2048    // tokens (2*1024)
#define TOPK 2

#define SLOT_CAP     6144     // padded routed slots (max 4992)
#define SHARED_HBASE 6144     // h-scratch row where shared-expert rows start
#define HROWS        8192     // 6144 routed + 2048 shared
#define MAX_TILES    48

// ---------------- scratch (device globals; no allocations) ----------------
__device__ int   g_rows[SLOT_CAP];          // slot -> token (-1 = padding)
__device__ float g_wts[SLOT_CAP];           // slot -> gate prob
__device__ int   g_tile_e[MAX_TILES];
__device__ int   g_tile_base[MAX_TILES];
__device__ int   g_num_tiles;
__device__ int   g_topk_idx[NTOK * TOPK];
__device__ float g_topk_prob[NTOK * TOPK];
__device__ float g_hbuf[(size_t)HROWS * NM];   // 64 MB intermediate h

__device__ __forceinline__ float silu_f(float v) {
    return v / (1.0f + __expf(-v));
}

// ---------------- routing: logits, top-2, sigmoid ----------------
__global__ void moe_route(const float* __restrict__ x,
                          const float* __restrict__ gw,
                          const float* __restrict__ beta) {
    int b = blockIdx.x;
    const float* xr = x + (size_t)b * NH;
    float acc[NE];
#pragma unroll
    for (int e = 0; e < NE; e++) acc[e] = 0.f;

    for (int h = threadIdx.x; h < NH; h += 256) {
        float xv = xr[h];
#pragma unroll
        for (int e = 0; e < NE; e++) acc[e] += xv * gw[e * NH + h];
    }
    // warp reduce
#pragma unroll
    for (int off = 16; off > 0; off >>= 1) {
#pragma unroll
        for (int e = 0; e < NE; e++)
            acc[e] += __shfl_down_sync(0xFFFFFFFFu, acc[e], off);
    }
    __shared__ float part[8][NE];
    int lane = threadIdx.x & 31, warp = threadIdx.x >> 5;
    if (lane == 0) {
#pragma unroll
        for (int e = 0; e < NE; e++) part[warp][e] = acc[e];
    }
    __syncthreads();
    if (threadIdx.x == 0) {
        float lg[NE];
#pragma unroll
        for (int e = 0; e < NE; e++) {
            float s = 0.f;
#pragma unroll
            for (int w = 0; w < 8; w++) s += part[w][e];
            lg[e] = s;
        }
        // top-2 on lg + beta (strict > keeps lowest index on ties, matching lax.top_k)
        int i1 = 0; float b1 = -1e30f;
#pragma unroll
        for (int e = 0; e < NE; e++) {
            float v = lg[e] + beta[e];
            if (v > b1) { b1 = v; i1 = e; }
        }
        int i2 = -1; float b2 = -1e30f;
#pragma unroll
        for (int e = 0; e < NE; e++) {
            if (e == i1) continue;
            float v = lg[e] + beta[e];
            if (v > b2) { b2 = v; i2 = e; }
        }
        g_topk_idx[2 * b + 0] = i1;
        g_topk_prob[2 * b + 0] = 1.f / (1.f + __expf(-lg[i1]));
        g_topk_idx[2 * b + 1] = i2;
        g_topk_prob[2 * b + 1] = 1.f / (1.f + __expf(-lg[i2]));
    }
}

// ---------------- build: counts -> padded segments -> scatter ----------------
__global__ void moe_build() {
    __shared__ int cnt[NE], fill[NE], seg[NE];
    int tid = threadIdx.x;
    for (int i = tid; i < SLOT_CAP; i += blockDim.x) g_rows[i] = -1;
    if (tid < NE) { cnt[tid] = 0; fill[tid] = 0; }
    __syncthreads();
    for (int i = tid; i < NTOK * TOPK; i += blockDim.x)
        atomicAdd(&cnt[g_topk_idx[i]], 1);
    __syncthreads();
    if (tid == 0) {
        int off = 0, nt = 0;
        for (int e = 0; e < NE; e++) {
            seg[e] = off;
            int tiles = (cnt[e] + 127) >> 7;
            for (int t = 0; t < tiles; t++) {
                g_tile_e[nt] = e;
                g_tile_base[nt] = off + (t << 7);
                nt++;
            }
            off += tiles << 7;
        }
        g_num_tiles = nt;
    }
    __syncthreads();
    for (int i = tid; i < NTOK * TOPK; i += blockDim.x) {
        int e = g_topk_idx[i];
        int p = seg[e] + atomicAdd(&fill[e], 1);
        g_rows[p] = i >> 1;
        g_wts[p]  = g_topk_prob[i];
    }
}

// ---------------- GEMM1: h = silu(x @ Wg) * (x @ Wu), into g_hbuf ----------------
// Tile: 128 rows x 64 cols (per matrix), KB=16, 256 threads, 8x4 micro per matrix.
template <bool SHARED>
__global__ void __launch_bounds__(256, 2)
moe_gemm1(const float* __restrict__ x,
          const float* __restrict__ Wg,   // [E,H,M] or [1,H,M]
          const float* __restrict__ Wu) {
    constexpr int TM = 128, TN = 64, KB = 16;
    int by = blockIdx.y;
    int base, e;
    if (SHARED) { base = by * TM; e = 0; }
    else {
        if (by >= g_num_tiles) return;
        e = g_tile_e[by];
        base = g_tile_base[by];
    }
    int m0 = blockIdx.x * TN;

    __shared__ float As[KB][TM + 1];
    __shared__ float Bgs[KB][TN];
    __shared__ float Bus[KB][TN];

    int tid = threadIdx.x;
    int tx = tid & 15, ty = tid >> 4;

    int a_kq = tid & 3;         // float4 within 16-wide k slab
    int a_r  = tid >> 2;        // row 0..63 (and +64)
    int tok0, tok1;
    if (SHARED) { tok0 = base + a_r; tok1 = base + a_r + 64; }
    else        { tok0 = g_rows[base + a_r]; tok1 = g_rows[base + a_r + 64]; }

    int b_c = (tid & 15) * 4;
    int b_k = tid >> 4;
    const float* wg = Wg + (size_t)e * NH * NM;
    const float* wu = Wu + (size_t)e * NH * NM;

    float accg[8][4], accu[8][4];
#pragma unroll
    for (int i = 0; i < 8; i++)
#pragma unroll
        for (int j = 0; j < 4; j++) { accg[i][j] = 0.f; accu[i][j] = 0.f; }

    const float4 z4 = make_float4(0.f, 0.f, 0.f, 0.f);

    for (int k0 = 0; k0 < NH; k0 += KB) {
        float4 va0 = (tok0 >= 0) ? *(const float4*)(x + (size_t)tok0 * NH + k0 + a_kq * 4) : z4;
        float4 va1 = (tok1 >= 0) ? *(const float4*)(x + (size_t)tok1 * NH + k0 + a_kq * 4) : z4;
        float4 vg = *(const float4*)(wg + (size_t)(k0 + b_k) * NM + m0 + b_c);
        float4 vu = *(const float4*)(wu + (size_t)(k0 + b_k) * NM + m0 + b_c);

        As[a_kq * 4 + 0][a_r] = va0.x;
        As[a_kq * 4 + 1][a_r] = va0.y;
        As[a_kq * 4 + 2][a_r] = va0.z;
        As[a_kq * 4 + 3][a_r] = va0.w;
        As[a_kq * 4 + 0][a_r + 64] = va1.x;
        As[a_kq * 4 + 1][a_r + 64] = va1.y;
        As[a_kq * 4 + 2][a_r + 64] = va1.z;
        As[a_kq * 4 + 3][a_r + 64] = va1.w;
        *(float4*)&Bgs[b_k][b_c] = vg;
        *(float4*)&Bus[b_k][b_c] = vu;
        __syncthreads();

#pragma unroll
        for (int k = 0; k < KB; k++) {
            float a[8];
#pragma unroll
            for (int i = 0; i < 8; i++) a[i] = As[k][ty * 8 + i];
            float4 bg = *(float4*)&Bgs[k][tx * 4];
            float4 bu = *(float4*)&Bus[k][tx * 4];
#pragma unroll
            for (int i = 0; i < 8; i++) {
                accg[i][0] += a[i] * bg.x;
                accg[i][1] += a[i] * bg.y;
                accg[i][2] += a[i] * bg.z;
                accg[i][3] += a[i] * bg.w;
                accu[i][0] += a[i] * bu.x;
                accu[i][1] += a[i] * bu.y;
                accu[i][2] += a[i] * bu.z;
                accu[i][3] += a[i] * bu.w;
            }
        }
        __syncthreads();
    }

    int hrow0 = (SHARED ? SHARED_HBASE : 0) + base;
#pragma unroll
    for (int i = 0; i < 8; i++) {
        int r = ty * 8 + i;
        float4 hv;
        hv.x = silu_f(accg[i][0]) * accu[i][0];
        hv.y = silu_f(accg[i][1]) * accu[i][1];
        hv.z = silu_f(accg[i][2]) * accu[i][2];
        hv.w = silu_f(accg[i][3]) * accu[i][3];
        *(float4*)&g_hbuf[(size_t)(hrow0 + r) * NM + m0 + tx * 4] = hv;
    }
}

// ---------------- GEMM2: out = h @ Wd (shared writes; routed atomicAdd * prob) ----------------
// Tile: 128x128, KB=16, 256 threads, 8x8 micro.
template <bool SHARED>
__global__ void __launch_bounds__(256, 2)
moe_gemm2(const float* __restrict__ Wd,   // [E,M,H] or [1,M,H]
          float* __restrict__ out) {
    constexpr int TM = 128, TN = 128, KB = 16;
    int by = blockIdx.y;
    int base, e;
    if (SHARED) { base = by * TM; e = 0; }
    else {
        if (by >= g_num_tiles) return;
        e = g_tile_e[by];
        base = g_tile_base[by];
    }
    int n0 = blockIdx.x * TN;

    __shared__ float As[KB][TM + 1];
    __shared__ float Bs[KB][TN];

    int tid = threadIdx.x;
    int tx = tid & 15, ty = tid >> 4;

    int a_kq = tid & 3;
    int a_r  = tid >> 2;
    size_t hrow0 = (size_t)((SHARED ? SHARED_HBASE : 0) + base + a_r);

    int b_c = (tid & 31) * 4;
    int b_k = tid >> 5;   // 0..7 (and +8)
    const float* wd = Wd + (size_t)e * NM * NH;

    float acc[8][8];
#pragma unroll
    for (int i = 0; i < 8; i++)
#pragma unroll
        for (int j = 0; j < 8; j++) acc[i][j] = 0.f;

    for (int k0 = 0; k0 < NM; k0 += KB) {
        float4 va0 = *(const float4*)&g_hbuf[hrow0 * NM + k0 + a_kq * 4];
        float4 va1 = *(const float4*)&g_hbuf[(hrow0 + 64) * NM + k0 + a_kq * 4];
        float4 vb0 = *(const float4*)(wd + (size_t)(k0 + b_k) * NH + n0 + b_c);
        float4 vb1 = *(const float4*)(wd + (size_t)(k0 + b_k + 8) * NH + n0 + b_c);

        As[a_kq * 4 + 0][a_r] = va0.x;
        As[a_kq * 4 + 1][a_r] = va0.y;
        As[a_kq * 4 + 2][a_r] = va0.z;
        As[a_kq * 4 + 3][a_r] = va0.w;
        As[a_kq * 4 + 0][a_r + 64] = va1.x;
        As[a_kq * 4 + 1][a_r + 64] = va1.y;
        As[a_kq * 4 + 2][a_r + 64] = va1.z;
        As[a_kq * 4 + 3][a_r + 64] = va1.w;
        *(float4*)&Bs[b_k][b_c] = vb0;
        *(float4*)&Bs[b_k + 8][b_c] = vb1;
        __syncthreads();

#pragma unroll
        for (int k = 0; k < KB; k++) {
            float a[8];
#pragma unroll
            for (int i = 0; i < 8; i++) a[i] = As[k][ty * 8 + i];
            float4 bl = *(float4*)&Bs[k][tx * 8];
            float4 bh = *(float4*)&Bs[k][tx * 8 + 4];
            float b[8] = {bl.x, bl.y, bl.z, bl.w, bh.x, bh.y, bh.z, bh.w};
#pragma unroll
            for (int i = 0; i < 8; i++)
#pragma unroll
                for (int j = 0; j < 8; j++)
                    acc[i][j] += a[i] * b[j];
        }
        __syncthreads();
    }

    if (SHARED) {
#pragma unroll
        for (int i = 0; i < 8; i++) {
            int token = base + ty * 8 + i;
            float4 lo = make_float4(acc[i][0], acc[i][1], acc[i][2], acc[i][3]);
            float4 hi = make_float4(acc[i][4], acc[i][5], acc[i][6], acc[i][7]);
            *(float4*)&out[(size_t)token * NH + n0 + tx * 8 + 0] = lo;
            *(float4*)&out[(size_t)token * NH + n0 + tx * 8 + 4] = hi;
        }
    } else {
#pragma unroll
        for (int i = 0; i < 8; i++) {
            int slot = base + ty * 8 + i;
            int token = g_rows[slot];
            if (token < 0) continue;
            float w = g_wts[slot];
#pragma unroll
            for (int j = 0; j < 8; j++)
                atomicAdd(&out[(size_t)token * NH + n0 + tx * 8 + j], acc[i][j] * w);
        }
    }
}

// ---------------- launch ----------------
extern "C" void kernel_launch(void* const* d_in, const int* in_sizes, int n_in,
                              void* d_out, int out_size) {
    const float* x    = (const float*)d_in[0];
    const float* gw   = (const float*)d_in[1];
    const float* beta = (const float*)d_in[2];
    const float* gpw  = (const float*)d_in[3];
    const float* upw  = (const float*)d_in[4];
    const float* dpw  = (const float*)d_in[5];
    const float* sgw  = (const float*)d_in[6];
    const float* suw  = (const float*)d_in[7];
    const float* sdw  = (const float*)d_in[8];
    float* out = (float*)d_out;

    moe_route<<<NTOK, 256>>>(x, gw, beta);
    moe_build<<<1, 512>>>();
    // routed gate/up + silu  (grid.y = max tiles; blocks past g_num_tiles exit)
    moe_gemm1<false><<<dim3(NM / 64, 40), 256>>>(x, gpw, upw);
    // shared expert gate/up + silu
    moe_gemm1<true><<<dim3(NM / 64, NTOK / 128), 256>>>(x, sgw, suw);
    // shared down-proj writes out (also serves as output init)
    moe_gemm2<true><<<dim3(NH / 128, NTOK / 128), 256>>>(sdw, out);
    // routed down-proj accumulates prob-weighted
    moe_gemm2<false><<<dim3(NH / 128, 40), 256>>>(dpw, out);
}

// round 4
// speedup vs baseline: 1.8348x; 1.8348x over previous
#include <cuda_runtime.h>
#include <cstdint>

#define NE   8
#define NH   1024
#define NM   2048
#define NTOK 2048
#define SLOT_CAP     6144
#define SHARED_HBASE 6144
#define HROWS        8192
#define MAX_TILES    48

#define AST  136   // A smem k-row stride (floats): 136 % 32 == 8 -> conflict-free
#define BST1 72    // B smem stride for N=64 tiles
#define BST2 136   // B smem stride for N=128 tiles

// ---------------- device scratch ----------------
__device__ int   g_rows[SLOT_CAP];
__device__ int   g_tile_e[MAX_TILES];
__device__ int   g_tile_base[MAX_TILES];
__device__ int   g_num_tiles;
__device__ int   g_topk_idx[NTOK * 2];
__device__ float g_topk_prob[NTOK * 2];
__device__ int   g_tok2slot[NTOK * 2];
__device__ float g_hbuf[(size_t)HROWS * NM];      // silu(g)*u
__device__ float g_eout[(size_t)SLOT_CAP * NH];   // routed expert outputs

// ---------------- helpers ----------------
__device__ __forceinline__ float to_tf32(float v) {
    uint32_t r;
    asm("cvt.rna.tf32.f32 %0, %1;" : "=r"(r) : "f"(v));
    return __uint_as_float(r);
}
__device__ __forceinline__ float silu_f(float v) { return v / (1.0f + __expf(-v)); }

// D += A(16x8) * B(8x8), tf32 inputs, f32 accum
__device__ __forceinline__ void mma8(float* d, const uint32_t* a, uint32_t b0, uint32_t b1) {
    asm volatile(
        "mma.sync.aligned.m16n8k8.row.col.f32.tf32.tf32.f32 "
        "{%0,%1,%2,%3},{%4,%5,%6,%7},{%8,%9},{%0,%1,%2,%3};"
        : "+f"(d[0]), "+f"(d[1]), "+f"(d[2]), "+f"(d[3])
        : "r"(a[0]), "r"(a[1]), "r"(a[2]), "r"(a[3]), "r"(b0), "r"(b1));
}

// ---------------- routing ----------------
__global__ void moe_route(const float* __restrict__ x,
                          const float* __restrict__ gw,
                          const float* __restrict__ beta) {
    int b = blockIdx.x;
    const float* xr = x + (size_t)b * NH;
    float acc[NE];
#pragma unroll
    for (int e = 0; e < NE; e++) acc[e] = 0.f;
    for (int h = threadIdx.x; h < NH; h += 256) {
        float xv = xr[h];
#pragma unroll
        for (int e = 0; e < NE; e++) acc[e] += xv * gw[e * NH + h];
    }
#pragma unroll
    for (int off = 16; off > 0; off >>= 1)
#pragma unroll
        for (int e = 0; e < NE; e++)
            acc[e] += __shfl_down_sync(0xFFFFFFFFu, acc[e], off);
    __shared__ float part[8][NE];
    int lane = threadIdx.x & 31, warp = threadIdx.x >> 5;
    if (lane == 0)
#pragma unroll
        for (int e = 0; e < NE; e++) part[warp][e] = acc[e];
    __syncthreads();
    if (threadIdx.x == 0) {
        float lg[NE];
#pragma unroll
        for (int e = 0; e < NE; e++) {
            float s = 0.f;
#pragma unroll
            for (int w = 0; w < 8; w++) s += part[w][e];
            lg[e] = s;
        }
        int i1 = 0; float b1 = -1e30f;
#pragma unroll
        for (int e = 0; e < NE; e++) {
            float v = lg[e] + beta[e];
            if (v > b1) { b1 = v; i1 = e; }
        }
        int i2 = -1; float b2 = -1e30f;
#pragma unroll
        for (int e = 0; e < NE; e++) {
            if (e == i1) continue;
            float v = lg[e] + beta[e];
            if (v > b2) { b2 = v; i2 = e; }
        }
        g_topk_idx[2 * b + 0] = i1;
        g_topk_prob[2 * b + 0] = 1.f / (1.f + __expf(-lg[i1]));
        g_topk_idx[2 * b + 1] = i2;
        g_topk_prob[2 * b + 1] = 1.f / (1.f + __expf(-lg[i2]));
    }
}

__global__ void moe_build() {
    __shared__ int cnt[NE], fill[NE], seg[NE];
    int tid = threadIdx.x;
    for (int i = tid; i < SLOT_CAP; i += blockDim.x) g_rows[i] = -1;
    if (tid < NE) { cnt[tid] = 0; fill[tid] = 0; }
    __syncthreads();
    for (int i = tid; i < NTOK * 2; i += blockDim.x)
        atomicAdd(&cnt[g_topk_idx[i]], 1);
    __syncthreads();
    if (tid == 0) {
        int off = 0, nt = 0;
        for (int e = 0; e < NE; e++) {
            seg[e] = off;
            int tiles = (cnt[e] + 127) >> 7;
            for (int t = 0; t < tiles; t++) {
                g_tile_e[nt] = e;
                g_tile_base[nt] = off + (t << 7);
                nt++;
            }
            off += tiles << 7;
        }
        g_num_tiles = nt;
    }
    __syncthreads();
    for (int i = tid; i < NTOK * 2; i += blockDim.x) {
        int e = g_topk_idx[i];
        int p = seg[e] + atomicAdd(&fill[e], 1);
        g_rows[p] = i >> 1;
        g_tok2slot[i] = p;
    }
}

// ---------------- GEMM1: h = silu(x@Wg)*(x@Wu), CTA 128m x 64n, 512 thr ----------------
#define SMEM1_FLOATS (2 * 32 * AST + 2 * 2 * 32 * BST1)
#define SMEM1_BYTES  (SMEM1_FLOATS * 4)

template <bool SHARED>
__global__ void __launch_bounds__(512, 1)
moe_gemm1_mma(const float* __restrict__ x,
              const float* __restrict__ Wg,
              const float* __restrict__ Wu) {
    extern __shared__ float sm[];
    int by = blockIdx.y, e, base;
    if (SHARED) { e = 0; base = by * 128; }
    else {
        if (by >= g_num_tiles) return;
        e = g_tile_e[by];
        base = g_tile_base[by];
    }
    const int m0 = blockIdx.x * 64;
    const float* wg = Wg + (size_t)e * NH * NM;
    const float* wu = Wu + (size_t)e * NH * NM;

    float* As = sm;                    // [2][32][AST]
    float* Bg = sm + 2 * 32 * AST;     // [2][32][BST1]
    float* Bu = Bg + 2 * 32 * BST1;

    const int tid = threadIdx.x;
    const int lane = tid & 31, wid = tid >> 5;
    const int j = lane & 3, g = lane >> 2;
    const int wm = (wid & 3) * 32, wn = (wid >> 2) * 16;

    // LDG assignments
    const int row_a = tid & 127, q0 = tid >> 7;          // q0 in 0..3
    int tok = SHARED ? (base + row_a) : g_rows[base + row_a];
    const bool okA = (tok >= 0);
    const float* ax = x + (size_t)(okA ? tok : 0) * NH;
    const int bn4 = (tid & 15) * 4, bk = tid >> 4;       // bk 0..31

    float dg[2][2][4], du[2][2][4];
#pragma unroll
    for (int a1 = 0; a1 < 2; a1++)
#pragma unroll
        for (int b1 = 0; b1 < 2; b1++)
#pragma unroll
            for (int c1 = 0; c1 < 4; c1++) { dg[a1][b1][c1] = 0.f; du[a1][b1][c1] = 0.f; }

    const float4 z4 = make_float4(0.f, 0.f, 0.f, 0.f);
    float4 va0, va1, vg, vu;
    // prefetch chunk 0
    va0 = okA ? *(const float4*)(ax + 4 * q0) : z4;
    va1 = okA ? *(const float4*)(ax + 4 * q0 + 16) : z4;
    vg = *(const float4*)(wg + (size_t)bk * NM + m0 + bn4);
    vu = *(const float4*)(wu + (size_t)bk * NM + m0 + bn4);

    const int KC = NH / 32;
    int buf = 0;
    {   // STS chunk 0
        float* asw = As;
        float* bgw = Bg;
        float* buw = Bu;
        asw[(4 * q0 + 0) * AST + row_a] = to_tf32(va0.x);
        asw[(4 * q0 + 1) * AST + row_a] = to_tf32(va0.y);
        asw[(4 * q0 + 2) * AST + row_a] = to_tf32(va0.z);
        asw[(4 * q0 + 3) * AST + row_a] = to_tf32(va0.w);
        asw[(4 * q0 + 16) * AST + row_a] = to_tf32(va1.x);
        asw[(4 * q0 + 17) * AST + row_a] = to_tf32(va1.y);
        asw[(4 * q0 + 18) * AST + row_a] = to_tf32(va1.z);
        asw[(4 * q0 + 19) * AST + row_a] = to_tf32(va1.w);
        float4 cg = make_float4(to_tf32(vg.x), to_tf32(vg.y), to_tf32(vg.z), to_tf32(vg.w));
        float4 cu = make_float4(to_tf32(vu.x), to_tf32(vu.y), to_tf32(vu.z), to_tf32(vu.w));
        *(float4*)&bgw[bk * BST1 + bn4] = cg;
        *(float4*)&buw[bk * BST1 + bn4] = cu;
    }
    __syncthreads();

    for (int kc = 0; kc < KC; kc++) {
        if (kc + 1 < KC) {
            int k0 = (kc + 1) * 32;
            va0 = okA ? *(const float4*)(ax + k0 + 4 * q0) : z4;
            va1 = okA ? *(const float4*)(ax + k0 + 4 * q0 + 16) : z4;
            vg = *(const float4*)(wg + (size_t)(k0 + bk) * NM + m0 + bn4);
            vu = *(const float4*)(wu + (size_t)(k0 + bk) * NM + m0 + bn4);
        }
        const float* as = As + buf * 32 * AST;
        const float* bg = Bg + buf * 32 * BST1;
        const float* bu = Bu + buf * 32 * BST1;
#pragma unroll
        for (int s = 0; s < 4; s++) {
            const int kA = 8 * s + j;
            uint32_t a[2][4];
#pragma unroll
            for (int mi = 0; mi < 2; mi++) {
                int r0 = wm + 16 * mi + g;
                a[mi][0] = __float_as_uint(as[kA * AST + r0]);
                a[mi][1] = __float_as_uint(as[kA * AST + r0 + 8]);
                a[mi][2] = __float_as_uint(as[(kA + 4) * AST + r0]);
                a[mi][3] = __float_as_uint(as[(kA + 4) * AST + r0 + 8]);
            }
#pragma unroll
            for (int ni = 0; ni < 2; ni++) {
                int c = wn + 8 * ni + g;
                uint32_t g0 = __float_as_uint(bg[kA * BST1 + c]);
                uint32_t g1 = __float_as_uint(bg[(kA + 4) * BST1 + c]);
                uint32_t u0 = __float_as_uint(bu[kA * BST1 + c]);
                uint32_t u1 = __float_as_uint(bu[(kA + 4) * BST1 + c]);
#pragma unroll
                for (int mi = 0; mi < 2; mi++) {
                    mma8(dg[mi][ni], a[mi], g0, g1);
                    mma8(du[mi][ni], a[mi], u0, u1);
                }
            }
        }
        if (kc + 1 < KC) {
            buf ^= 1;
            float* asw = As + buf * 32 * AST;
            float* bgw = Bg + buf * 32 * BST1;
            float* buw = Bu + buf * 32 * BST1;
            asw[(4 * q0 + 0) * AST + row_a] = to_tf32(va0.x);
            asw[(4 * q0 + 1) * AST + row_a] = to_tf32(va0.y);
            asw[(4 * q0 + 2) * AST + row_a] = to_tf32(va0.z);
            asw[(4 * q0 + 3) * AST + row_a] = to_tf32(va0.w);
            asw[(4 * q0 + 16) * AST + row_a] = to_tf32(va1.x);
            asw[(4 * q0 + 17) * AST + row_a] = to_tf32(va1.y);
            asw[(4 * q0 + 18) * AST + row_a] = to_tf32(va1.z);
            asw[(4 * q0 + 19) * AST + row_a] = to_tf32(va1.w);
            float4 cg = make_float4(to_tf32(vg.x), to_tf32(vg.y), to_tf32(vg.z), to_tf32(vg.w));
            float4 cu = make_float4(to_tf32(vu.x), to_tf32(vu.y), to_tf32(vu.z), to_tf32(vu.w));
            *(float4*)&bgw[bk * BST1 + bn4] = cg;
            *(float4*)&buw[bk * BST1 + bn4] = cu;
            __syncthreads();
        }
    }

    // epilogue: h = silu(g)*u
    const int hb = (SHARED ? SHARED_HBASE : 0) + base;
#pragma unroll
    for (int mi = 0; mi < 2; mi++)
#pragma unroll
        for (int ni = 0; ni < 2; ni++) {
            int r = wm + 16 * mi + g;
            int col = m0 + wn + 8 * ni + 2 * j;
            float2 h0, h1;
            h0.x = silu_f(dg[mi][ni][0]) * du[mi][ni][0];
            h0.y = silu_f(dg[mi][ni][1]) * du[mi][ni][1];
            h1.x = silu_f(dg[mi][ni][2]) * du[mi][ni][2];
            h1.y = silu_f(dg[mi][ni][3]) * du[mi][ni][3];
            *(float2*)&g_hbuf[(size_t)(hb + r) * NM + col] = h0;
            *(float2*)&g_hbuf[(size_t)(hb + r + 8) * NM + col] = h1;
        }
}

// ---------------- GEMM2: out/eout = h @ Wd, CTA 128m x 128n, 512 thr ----------------
#define SMEM2_FLOATS (2 * 32 * AST + 2 * 32 * BST2)
#define SMEM2_BYTES  (SMEM2_FLOATS * 4)

template <bool SHARED>
__global__ void __launch_bounds__(512, 1)
moe_gemm2_mma(const float* __restrict__ Wd, float* __restrict__ out) {
    extern __shared__ float sm[];
    int by = blockIdx.y, e, base;
    if (SHARED) { e = 0; base = by * 128; }
    else {
        if (by >= g_num_tiles) return;
        e = g_tile_e[by];
        base = g_tile_base[by];
    }
    const int n0 = blockIdx.x * 128;
    const float* wd = Wd + (size_t)e * NM * NH;
    const int hb = (SHARED ? SHARED_HBASE : 0) + base;

    float* As = sm;                    // [2][32][AST]
    float* Bs = sm + 2 * 32 * AST;     // [2][32][BST2]

    const int tid = threadIdx.x;
    const int lane = tid & 31, wid = tid >> 5;
    const int j = lane & 3, g = lane >> 2;
    const int wm = (wid & 3) * 32, wn = (wid >> 2) * 32;

    const int row_a = tid & 127, q0 = tid >> 7;
    const float* ax = g_hbuf + (size_t)(hb + row_a) * NM;
    const int bn4 = (tid & 31) * 4, bk = tid >> 5;    // bk 0..15, +16 for u=1

    float d[2][4][4];
#pragma unroll
    for (int a1 = 0; a1 < 2; a1++)
#pragma unroll
        for (int b1 = 0; b1 < 4; b1++)
#pragma unroll
            for (int c1 = 0; c1 < 4; c1++) d[a1][b1][c1] = 0.f;

    float4 va0, va1, vb0, vb1;
    va0 = *(const float4*)(ax + 4 * q0);
    va1 = *(const float4*)(ax + 4 * q0 + 16);
    vb0 = *(const float4*)(wd + (size_t)bk * NH + n0 + bn4);
    vb1 = *(const float4*)(wd + (size_t)(bk + 16) * NH + n0 + bn4);

    const int KC = NM / 32;
    int buf = 0;
    {
        float* asw = As;
        float* bsw = Bs;
        asw[(4 * q0 + 0) * AST + row_a] = to_tf32(va0.x);
        asw[(4 * q0 + 1) * AST + row_a] = to_tf32(va0.y);
        asw[(4 * q0 + 2) * AST + row_a] = to_tf32(va0.z);
        asw[(4 * q0 + 3) * AST + row_a] = to_tf32(va0.w);
        asw[(4 * q0 + 16) * AST + row_a] = to_tf32(va1.x);
        asw[(4 * q0 + 17) * AST + row_a] = to_tf32(va1.y);
        asw[(4 * q0 + 18) * AST + row_a] = to_tf32(va1.z);
        asw[(4 * q0 + 19) * AST + row_a] = to_tf32(va1.w);
        float4 c0 = make_float4(to_tf32(vb0.x), to_tf32(vb0.y), to_tf32(vb0.z), to_tf32(vb0.w));
        float4 c1 = make_float4(to_tf32(vb1.x), to_tf32(vb1.y), to_tf32(vb1.z), to_tf32(vb1.w));
        *(float4*)&bsw[bk * BST2 + bn4] = c0;
        *(float4*)&bsw[(bk + 16) * BST2 + bn4] = c1;
    }
    __syncthreads();

    for (int kc = 0; kc < KC; kc++) {
        if (kc + 1 < KC) {
            int k0 = (kc + 1) * 32;
            va0 = *(const float4*)(ax + k0 + 4 * q0);
            va1 = *(const float4*)(ax + k0 + 4 * q0 + 16);
            vb0 = *(const float4*)(wd + (size_t)(k0 + bk) * NH + n0 + bn4);
            vb1 = *(const float4*)(wd + (size_t)(k0 + bk + 16) * NH + n0 + bn4);
        }
        const float* as = As + buf * 32 * AST;
        const float* bs = Bs + buf * 32 * BST2;
#pragma unroll
        for (int s = 0; s < 4; s++) {
            const int kA = 8 * s + j;
            uint32_t a[2][4];
#pragma unroll
            for (int mi = 0; mi < 2; mi++) {
                int r0 = wm + 16 * mi + g;
                a[mi][0] = __float_as_uint(as[kA * AST + r0]);
                a[mi][1] = __float_as_uint(as[kA * AST + r0 + 8]);
                a[mi][2] = __float_as_uint(as[(kA + 4) * AST + r0]);
                a[mi][3] = __float_as_uint(as[(kA + 4) * AST + r0 + 8]);
            }
#pragma unroll
            for (int ni = 0; ni < 4; ni++) {
                int c = wn + 8 * ni + g;
                uint32_t b0 = __float_as_uint(bs[kA * BST2 + c]);
                uint32_t b1 = __float_as_uint(bs[(kA + 4) * BST2 + c]);
#pragma unroll
                for (int mi = 0; mi < 2; mi++)
                    mma8(d[mi][ni], a[mi], b0, b1);
            }
        }
        if (kc + 1 < KC) {
            buf ^= 1;
            float* asw = As + buf * 32 * AST;
            float* bsw = Bs + buf * 32 * BST2;
            asw[(4 * q0 + 0) * AST + row_a] = to_tf32(va0.x);
            asw[(4 * q0 + 1) * AST + row_a] = to_tf32(va0.y);
            asw[(4 * q0 + 2) * AST + row_a] = to_tf32(va0.z);
            asw[(4 * q0 + 3) * AST + row_a] = to_tf32(va0.w);
            asw[(4 * q0 + 16) * AST + row_a] = to_tf32(va1.x);
            asw[(4 * q0 + 17) * AST + row_a] = to_tf32(va1.y);
            asw[(4 * q0 + 18) * AST + row_a] = to_tf32(va1.z);
            asw[(4 * q0 + 19) * AST + row_a] = to_tf32(va1.w);
            float4 c0 = make_float4(to_tf32(vb0.x), to_tf32(vb0.y), to_tf32(vb0.z), to_tf32(vb0.w));
            float4 c1 = make_float4(to_tf32(vb1.x), to_tf32(vb1.y), to_tf32(vb1.z), to_tf32(vb1.w));
            *(float4*)&bsw[bk * BST2 + bn4] = c0;
            *(float4*)&bsw[(bk + 16) * BST2 + bn4] = c1;
            __syncthreads();
        }
    }

#pragma unroll
    for (int mi = 0; mi < 2; mi++)
#pragma unroll
        for (int ni = 0; ni < 4; ni++) {
            int r = base + wm + 16 * mi + g;
            int col = n0 + wn + 8 * ni + 2 * j;
            float* dst0 = SHARED ? (out + (size_t)r * NH + col)
                                 : (g_eout + (size_t)r * NH + col);
            float* dst1 = SHARED ? (out + (size_t)(r + 8) * NH + col)
                                 : (g_eout + (size_t)(r + 8) * NH + col);
            *(float2*)dst0 = make_float2(d[mi][ni][0], d[mi][ni][1]);
            *(float2*)dst1 = make_float2(d[mi][ni][2], d[mi][ni][3]);
        }
}

// ---------------- combine ----------------
__global__ void moe_combine(float* __restrict__ out) {
    int t = blockIdx.x;
    int h = threadIdx.x * 4;
    int s0 = g_tok2slot[2 * t + 0], s1 = g_tok2slot[2 * t + 1];
    float p0 = g_topk_prob[2 * t + 0], p1 = g_topk_prob[2 * t + 1];
    float4 o = *(float4*)(out + (size_t)t * NH + h);
    float4 a = *(const float4*)(g_eout + (size_t)s0 * NH + h);
    float4 b = *(const float4*)(g_eout + (size_t)s1 * NH + h);
    o.x += p0 * a.x + p1 * b.x;
    o.y += p0 * a.y + p1 * b.y;
    o.z += p0 * a.z + p1 * b.z;
    o.w += p0 * a.w + p1 * b.w;
    *(float4*)(out + (size_t)t * NH + h) = o;
}

// ---------------- launch ----------------
extern "C" void kernel_launch(void* const* d_in, const int* in_sizes, int n_in,
                              void* d_out, int out_size) {
    const float* x    = (const float*)d_in[0];
    const float* gw   = (const float*)d_in[1];
    const float* beta = (const float*)d_in[2];
    const float* gpw  = (const float*)d_in[3];
    const float* upw  = (const float*)d_in[4];
    const float* dpw  = (const float*)d_in[5];
    const float* sgw  = (const float*)d_in[6];
    const float* suw  = (const float*)d_in[7];
    const float* sdw  = (const float*)d_in[8];
    float* out = (float*)d_out;

    cudaFuncSetAttribute(moe_gemm1_mma<false>, cudaFuncAttributeMaxDynamicSharedMemorySize, SMEM1_BYTES);
    cudaFuncSetAttribute(moe_gemm1_mma<true>,  cudaFuncAttributeMaxDynamicSharedMemorySize, SMEM1_BYTES);
    cudaFuncSetAttribute(moe_gemm2_mma<false>, cudaFuncAttributeMaxDynamicSharedMemorySize, SMEM2_BYTES);
    cudaFuncSetAttribute(moe_gemm2_mma<true>,  cudaFuncAttributeMaxDynamicSharedMemorySize, SMEM2_BYTES);

    moe_route<<<NTOK, 256>>>(x, gw, beta);
    moe_build<<<1, 512>>>();

    moe_gemm1_mma<false><<<dim3(NM / 64, 40), 512, SMEM1_BYTES>>>(x, gpw, upw);
    moe_gemm1_mma<true> <<<dim3(NM / 64, NTOK / 128), 512, SMEM1_BYTES>>>(x, sgw, suw);

    moe_gemm2_mma<true> <<<dim3(NH / 128, NTOK / 128), 512, SMEM2_BYTES>>>(sdw, out);
    moe_gemm2_mma<false><<<dim3(NH / 128, 40), 512, SMEM2_BYTES>>>(dpw, out);

    moe_combine<<<NTOK, 256>>>(out);
}

// round 7
// speedup vs baseline: 2.0893x; 1.1387x over previous
#include <cuda_runtime.h>
#include <cstdint>

#define NE   8
#define NH   1024
#define NM   2048
#define NTOK 2048
#define SLOT_CAP     6144
#define SHARED_HBASE 6144
#define HROWS        8192
#define MAX_TILES    48

// A smem: [16 kgroups][8 mblocks][8 pairs][4 slots] + pad -> kgroup stride 264 floats
#define AKG  264
#define A_BUF 4224          // 16 * 264 floats
#define BRS  264            // B row stride (128 n * 2 interleaved + 8 pad)
#define B1_BUF 8448         // 32 * 264 (gate/up interleaved)
#define B2_BUF 4224         // 16 * 264 (k, k+4 interleaved)

// ---------------- device scratch ----------------
__device__ int   g_rows[SLOT_CAP];
__device__ int   g_tile_e[MAX_TILES];
__device__ int   g_tile_base[MAX_TILES];
__device__ int   g_num_tiles;
__device__ int   g_topk_idx[NTOK * 2];
__device__ float g_topk_prob[NTOK * 2];
__device__ int   g_tok2slot[NTOK * 2];
__device__ float g_hbuf[(size_t)HROWS * NM];
__device__ float g_eout[(size_t)SLOT_CAP * NH];

// ---------------- helpers ----------------
__device__ __forceinline__ float to_tf32(float v) {
    uint32_t r;
    asm("cvt.rna.tf32.f32 %0, %1;" : "=r"(r) : "f"(v));
    return __uint_as_float(r);
}
__device__ __forceinline__ float silu_f(float v) { return v / (1.0f + __expf(-v)); }

__device__ __forceinline__ void mma8(float* d, const uint32_t* a, uint32_t b0, uint32_t b1) {
    asm volatile(
        "mma.sync.aligned.m16n8k8.row.col.f32.tf32.tf32.f32 "
        "{%0,%1,%2,%3},{%4,%5,%6,%7},{%8,%9},{%0,%1,%2,%3};"
        : "+f"(d[0]), "+f"(d[1]), "+f"(d[2]), "+f"(d[3])
        : "r"(a[0]), "r"(a[1]), "r"(a[2]), "r"(a[3]), "r"(b0), "r"(b1));
}

// A tile store: element (k 0..31, r 0..127) ->
//   kg = (k>>3)*4 + (k&3); addr = kg*AKG + (r>>4)*32 + (r&7)*4 + slot
//   slot = (((k>>2)&1)*2 + ((r>>3)&1)) ^ (((r>>4)&1)*2)
__device__ __forceinline__ void sts_a8(float* as, int row_a, int q0,
                                       float4 v0, float4 v1) {
    int blk = row_a >> 4;
    int rbase = blk * 32 + (row_a & 7) * 4 + ((row_a >> 3) & 1);
    int h = ((q0 & 1) ^ (blk & 1)) << 1;
    int kg0 = ((q0 >> 1) << 2);
    float* p0 = as + kg0 * AKG + rbase + h;
    p0[0 * AKG] = to_tf32(v0.x);
    p0[1 * AKG] = to_tf32(v0.y);
    p0[2 * AKG] = to_tf32(v0.z);
    p0[3 * AKG] = to_tf32(v0.w);
    float* p1 = p0 + 8 * AKG;
    p1[0 * AKG] = to_tf32(v1.x);
    p1[1 * AKG] = to_tf32(v1.y);
    p1[2 * AKG] = to_tf32(v1.z);
    p1[3 * AKG] = to_tf32(v1.w);
}

// Load both 16-row A fragments (blocks ablk0, ablk0+1; ablk0 even)
__device__ __forceinline__ void lds_a2(const float* as, int kgj, int ablk0, int g,
                                       uint32_t a[2][4]) {
    float4 f0 = *(const float4*)&as[kgj + ablk0 * 32 + g * 4];
    a[0][0] = __float_as_uint(f0.x); a[0][1] = __float_as_uint(f0.y);
    a[0][2] = __float_as_uint(f0.z); a[0][3] = __float_as_uint(f0.w);
    float4 f1 = *(const float4*)&as[kgj + (ablk0 + 1) * 32 + g * 4];
    a[1][0] = __float_as_uint(f1.z); a[1][1] = __float_as_uint(f1.w);
    a[1][2] = __float_as_uint(f1.x); a[1][3] = __float_as_uint(f1.y);
}

// ---------------- routing ----------------
__global__ void moe_route(const float* __restrict__ x,
                          const float* __restrict__ gw,
                          const float* __restrict__ beta) {
    int b = blockIdx.x;
    const float* xr = x + (size_t)b * NH;
    float acc[NE];
#pragma unroll
    for (int e = 0; e < NE; e++) acc[e] = 0.f;
    for (int h = threadIdx.x; h < NH; h += 256) {
        float xv = xr[h];
#pragma unroll
        for (int e = 0; e < NE; e++) acc[e] += xv * gw[e * NH + h];
    }
#pragma unroll
    for (int off = 16; off > 0; off >>= 1)
#pragma unroll
        for (int e = 0; e < NE; e++)
            acc[e] += __shfl_down_sync(0xFFFFFFFFu, acc[e], off);
    __shared__ float part[8][NE];
    int lane = threadIdx.x & 31, warp = threadIdx.x >> 5;
    if (lane == 0)
#pragma unroll
        for (int e = 0; e < NE; e++) part[warp][e] = acc[e];
    __syncthreads();
    if (threadIdx.x == 0) {
        float lg[NE];
#pragma unroll
        for (int e = 0; e < NE; e++) {
            float s = 0.f;
#pragma unroll
            for (int w = 0; w < 8; w++) s += part[w][e];
            lg[e] = s;
        }
        int i1 = 0; float b1 = -1e30f;
#pragma unroll
        for (int e = 0; e < NE; e++) {
            float v = lg[e] + beta[e];
            if (v > b1) { b1 = v; i1 = e; }
        }
        int i2 = -1; float b2 = -1e30f;
#pragma unroll
        for (int e = 0; e < NE; e++) {
            if (e == i1) continue;
            float v = lg[e] + beta[e];
            if (v > b2) { b2 = v; i2 = e; }
        }
        g_topk_idx[2 * b + 0] = i1;
        g_topk_prob[2 * b + 0] = 1.f / (1.f + __expf(-lg[i1]));
        g_topk_idx[2 * b + 1] = i2;
        g_topk_prob[2 * b + 1] = 1.f / (1.f + __expf(-lg[i2]));
    }
}

__global__ void moe_build() {
    __shared__ int cnt[NE], fill[NE], seg[NE];
    int tid = threadIdx.x;
    for (int i = tid; i < SLOT_CAP; i += blockDim.x) g_rows[i] = -1;
    if (tid < NE) { cnt[tid] = 0; fill[tid] = 0; }
    __syncthreads();
    for (int i = tid; i < NTOK * 2; i += blockDim.x)
        atomicAdd(&cnt[g_topk_idx[i]], 1);
    __syncthreads();
    if (tid == 0) {
        int off = 0, nt = 0;
        for (int e = 0; e < NE; e++) {
            seg[e] = off;
            int tiles = (cnt[e] + 127) >> 7;
            for (int t = 0; t < tiles; t++) {
                g_tile_e[nt] = e;
                g_tile_base[nt] = off + (t << 7);
                nt++;
            }
            off += tiles << 7;
        }
        g_num_tiles = nt;
    }
    __syncthreads();
    for (int i = tid; i < NTOK * 2; i += blockDim.x) {
        int e = g_topk_idx[i];
        int p = seg[e] + atomicAdd(&fill[e], 1);
        g_rows[p] = i >> 1;
        g_tok2slot[i] = p;
    }
}

// ---------------- GEMM1: h = silu(x@Wg)*(x@Wu), CTA 128m x 128n, 512 thr ----------------
#define SMEM1_BYTES ((2 * A_BUF + 2 * B1_BUF) * 4)

template <bool SHARED>
__global__ void __launch_bounds__(512)
moe_gemm1_mma(const float* __restrict__ x,
              const float* __restrict__ Wg,
              const float* __restrict__ Wu) {
    extern __shared__ float sm[];
    int by = blockIdx.y, e, base;
    if (SHARED) { e = 0; base = by * 128; }
    else {
        if (by >= g_num_tiles) return;
        e = g_tile_e[by];
        base = g_tile_base[by];
    }
    const int m0 = blockIdx.x * 128;
    const float* wg = Wg + (size_t)e * NH * NM;
    const float* wu = Wu + (size_t)e * NH * NM;

    float* As = sm;                   // [2][A_BUF]
    float* Bs = sm + 2 * A_BUF;       // [2][B1_BUF] gate/up interleaved

    const int tid = threadIdx.x;
    const int lane = tid & 31, wid = tid >> 5;
    const int j = lane & 3, g = lane >> 2;
    const int wm = (wid & 3) * 32, wn = (wid >> 2) * 32;
    const int ablk0 = (wid & 3) * 2;

    const int row_a = tid & 127, q0 = tid >> 7;
    int tok = SHARED ? (base + row_a) : g_rows[base + row_a];
    const bool okA = (tok >= 0);
    const float* ax = x + (size_t)(okA ? tok : 0) * NH;
    const int bn4 = (tid & 31) * 4, bk = tid >> 5;   // bk 0..15, +16

    float dg[2][4][4], du[2][4][4];
#pragma unroll
    for (int a1 = 0; a1 < 2; a1++)
#pragma unroll
        for (int b1 = 0; b1 < 4; b1++)
#pragma unroll
            for (int c1 = 0; c1 < 4; c1++) { dg[a1][b1][c1] = 0.f; du[a1][b1][c1] = 0.f; }

    const float4 z4 = make_float4(0.f, 0.f, 0.f, 0.f);
    float4 va0, va1, vg0, vu0, vg1, vu1;
    va0 = okA ? *(const float4*)(ax + 4 * q0) : z4;
    va1 = okA ? *(const float4*)(ax + 4 * q0 + 16) : z4;
    vg0 = *(const float4*)(wg + (size_t)bk * NM + m0 + bn4);
    vu0 = *(const float4*)(wu + (size_t)bk * NM + m0 + bn4);
    vg1 = *(const float4*)(wg + (size_t)(bk + 16) * NM + m0 + bn4);
    vu1 = *(const float4*)(wu + (size_t)(bk + 16) * NM + m0 + bn4);

    const int KC = NH / 32;
    int buf = 0;
    {
        sts_a8(As, row_a, q0, va0, va1);
        float* b = Bs + bk * BRS + bn4 * 2;
        float4 w0 = make_float4(to_tf32(vg0.x), to_tf32(vu0.x), to_tf32(vg0.y), to_tf32(vu0.y));
        float4 w1 = make_float4(to_tf32(vg0.z), to_tf32(vu0.z), to_tf32(vg0.w), to_tf32(vu0.w));
        *(float4*)(b) = w0; *(float4*)(b + 4) = w1;
        float* b2 = b + 16 * BRS;
        float4 w2 = make_float4(to_tf32(vg1.x), to_tf32(vu1.x), to_tf32(vg1.y), to_tf32(vu1.y));
        float4 w3 = make_float4(to_tf32(vg1.z), to_tf32(vu1.z), to_tf32(vg1.w), to_tf32(vu1.w));
        *(float4*)(b2) = w2; *(float4*)(b2 + 4) = w3;
    }
    __syncthreads();

    for (int kc = 0; kc < KC; kc++) {
        if (kc + 1 < KC) {
            int k0 = (kc + 1) * 32;
            va0 = okA ? *(const float4*)(ax + k0 + 4 * q0) : z4;
            va1 = okA ? *(const float4*)(ax + k0 + 4 * q0 + 16) : z4;
            vg0 = *(const float4*)(wg + (size_t)(k0 + bk) * NM + m0 + bn4);
            vu0 = *(const float4*)(wu + (size_t)(k0 + bk) * NM + m0 + bn4);
            vg1 = *(const float4*)(wg + (size_t)(k0 + bk + 16) * NM + m0 + bn4);
            vu1 = *(const float4*)(wu + (size_t)(k0 + bk + 16) * NM + m0 + bn4);
        }
        const float* as = As + buf * A_BUF;
        const float* bs = Bs + buf * B1_BUF;
#pragma unroll
        for (int s = 0; s < 4; s++) {
            const int kgj = (4 * s + j) * AKG;      // A kgroup row
            const int krj = (8 * s + j) * BRS;      // B k row
            uint32_t a[2][4];
            lds_a2(as, kgj, ablk0, g, a);
#pragma unroll
            for (int ni = 0; ni < 4; ni++) {
                int c2 = (wn + 8 * ni + g) * 2;
                float2 p0 = *(const float2*)&bs[krj + c2];
                float2 p1 = *(const float2*)&bs[krj + 4 * BRS + c2];
                uint32_t g0 = __float_as_uint(p0.x), u0 = __float_as_uint(p0.y);
                uint32_t g1 = __float_as_uint(p1.x), u1 = __float_as_uint(p1.y);
#pragma unroll
                for (int mi = 0; mi < 2; mi++) {
                    mma8(dg[mi][ni], a[mi], g0, g1);
                    mma8(du[mi][ni], a[mi], u0, u1);
                }
            }
        }
        if (kc + 1 < KC) {
            buf ^= 1;
            float* asw = As + buf * A_BUF;
            float* bsw = Bs + buf * B1_BUF;
            sts_a8(asw, row_a, q0, va0, va1);
            float* b = bsw + bk * BRS + bn4 * 2;
            float4 w0 = make_float4(to_tf32(vg0.x), to_tf32(vu0.x), to_tf32(vg0.y), to_tf32(vu0.y));
            float4 w1 = make_float4(to_tf32(vg0.z), to_tf32(vu0.z), to_tf32(vg0.w), to_tf32(vu0.w));
            *(float4*)(b) = w0; *(float4*)(b + 4) = w1;
            float* b2 = b + 16 * BRS;
            float4 w2 = make_float4(to_tf32(vg1.x), to_tf32(vu1.x), to_tf32(vg1.y), to_tf32(vu1.y));
            float4 w3 = make_float4(to_tf32(vg1.z), to_tf32(vu1.z), to_tf32(vg1.w), to_tf32(vu1.w));
            *(float4*)(b2) = w2; *(float4*)(b2 + 4) = w3;
            __syncthreads();
        }
    }

    const int hb = (SHARED ? SHARED_HBASE : 0) + base;
#pragma unroll
    for (int mi = 0; mi < 2; mi++)
#pragma unroll
        for (int ni = 0; ni < 4; ni++) {
            int r = hb + wm + 16 * mi + g;
            int col = m0 + wn + 8 * ni + 2 * j;
            float2 h0, h1;
            h0.x = silu_f(dg[mi][ni][0]) * du[mi][ni][0];
            h0.y = silu_f(dg[mi][ni][1]) * du[mi][ni][1];
            h1.x = silu_f(dg[mi][ni][2]) * du[mi][ni][2];
            h1.y = silu_f(dg[mi][ni][3]) * du[mi][ni][3];
            *(float2*)&g_hbuf[(size_t)r * NM + col] = h0;
            *(float2*)&g_hbuf[(size_t)(r + 8) * NM + col] = h1;
        }
}

// ---------------- GEMM2: out/eout = h @ Wd, CTA 128m x 128n, 512 thr ----------------
#define SMEM2_BYTES ((2 * A_BUF + 2 * B2_BUF) * 4)

template <bool SHARED>
__global__ void __launch_bounds__(512)
moe_gemm2_mma(const float* __restrict__ Wd, float* __restrict__ out) {
    extern __shared__ float sm[];
    int by = blockIdx.y, e, base;
    if (SHARED) { e = 0; base = by * 128; }
    else {
        if (by >= g_num_tiles) return;
        e = g_tile_e[by];
        base = g_tile_base[by];
    }
    const int n0 = blockIdx.x * 128;
    const float* wd = Wd + (size_t)e * NM * NH;
    const int hb = (SHARED ? SHARED_HBASE : 0) + base;

    float* As = sm;                   // [2][A_BUF]
    float* Bs = sm + 2 * A_BUF;       // [2][B2_BUF] (k, k+4) interleaved

    const int tid = threadIdx.x;
    const int lane = tid & 31, wid = tid >> 5;
    const int j = lane & 3, g = lane >> 2;
    const int wm = (wid & 3) * 32, wn = (wid >> 2) * 32;
    const int ablk0 = (wid & 3) * 2;

    const int row_a = tid & 127, q0 = tid >> 7;
    const float* ax = g_hbuf + (size_t)(hb + row_a) * NM;
    const int bn4 = (tid & 31) * 4;
    const int kb = tid >> 5;                          // 0..15
    const int klo = ((kb >> 2) << 3) + (kb & 3);      // pair base k

    float d[2][4][4];
#pragma unroll
    for (int a1 = 0; a1 < 2; a1++)
#pragma unroll
        for (int b1 = 0; b1 < 4; b1++)
#pragma unroll
            for (int c1 = 0; c1 < 4; c1++) d[a1][b1][c1] = 0.f;

    float4 va0, va1, vb0, vb1;
    va0 = *(const float4*)(ax + 4 * q0);
    va1 = *(const float4*)(ax + 4 * q0 + 16);
    vb0 = *(const float4*)(wd + (size_t)klo * NH + n0 + bn4);
    vb1 = *(const float4*)(wd + (size_t)(klo + 4) * NH + n0 + bn4);

    const int KC = NM / 32;
    int buf = 0;
    {
        sts_a8(As, row_a, q0, va0, va1);
        float* b = Bs + kb * BRS + bn4 * 2;
        float4 w0 = make_float4(to_tf32(vb0.x), to_tf32(vb1.x), to_tf32(vb0.y), to_tf32(vb1.y));
        float4 w1 = make_float4(to_tf32(vb0.z), to_tf32(vb1.z), to_tf32(vb0.w), to_tf32(vb1.w));
        *(float4*)(b) = w0; *(float4*)(b + 4) = w1;
    }
    __syncthreads();

    for (int kc = 0; kc < KC; kc++) {
        if (kc + 1 < KC) {
            int k0 = (kc + 1) * 32;
            va0 = *(const float4*)(ax + k0 + 4 * q0);
            va1 = *(const float4*)(ax + k0 + 4 * q0 + 16);
            vb0 = *(const float4*)(wd + (size_t)(k0 + klo) * NH + n0 + bn4);
            vb1 = *(const float4*)(wd + (size_t)(k0 + klo + 4) * NH + n0 + bn4);
        }
        const float* as = As + buf * A_BUF;
        const float* bs = Bs + buf * B2_BUF;
#pragma unroll
        for (int s = 0; s < 4; s++) {
            const int kgj = (4 * s + j) * AKG;   // same row index for A kgroup and B pair-row
            uint32_t a[2][4];
            lds_a2(as, kgj, ablk0, g, a);
#pragma unroll
            for (int ni = 0; ni < 4; ni++) {
                int c2 = (wn + 8 * ni + g) * 2;
                float2 p = *(const float2*)&bs[kgj + c2];
                uint32_t b0 = __float_as_uint(p.x), b1 = __float_as_uint(p.y);
#pragma unroll
                for (int mi = 0; mi < 2; mi++)
                    mma8(d[mi][ni], a[mi], b0, b1);
            }
        }
        if (kc + 1 < KC) {
            buf ^= 1;
            float* asw = As + buf * A_BUF;
            float* bsw = Bs + buf * B2_BUF;
            sts_a8(asw, row_a, q0, va0, va1);
            float* b = bsw + kb * BRS + bn4 * 2;
            float4 w0 = make_float4(to_tf32(vb0.x), to_tf32(vb1.x), to_tf32(vb0.y), to_tf32(vb1.y));
            float4 w1 = make_float4(to_tf32(vb0.z), to_tf32(vb1.z), to_tf32(vb0.w), to_tf32(vb1.w));
            *(float4*)(b) = w0; *(float4*)(b + 4) = w1;
            __syncthreads();
        }
    }

#pragma unroll
    for (int mi = 0; mi < 2; mi++)
#pragma unroll
        for (int ni = 0; ni < 4; ni++) {
            int r = base + wm + 16 * mi + g;
            int col = n0 + wn + 8 * ni + 2 * j;
            float* dst0 = SHARED ? (out + (size_t)r * NH + col)
                                 : (g_eout + (size_t)r * NH + col);
            float* dst1 = SHARED ? (out + (size_t)(r + 8) * NH + col)
                                 : (g_eout + (size_t)(r + 8) * NH + col);
            *(float2*)dst0 = make_float2(d[mi][ni][0], d[mi][ni][1]);
            *(float2*)dst1 = make_float2(d[mi][ni][2], d[mi][ni][3]);
        }
}

// ---------------- combine ----------------
__global__ void moe_combine(float* __restrict__ out) {
    int t = blockIdx.x;
    int h = threadIdx.x * 4;
    int s0 = g_tok2slot[2 * t + 0], s1 = g_tok2slot[2 * t + 1];
    float p0 = g_topk_prob[2 * t + 0], p1 = g_topk_prob[2 * t + 1];
    float4 o = *(float4*)(out + (size_t)t * NH + h);
    float4 a = *(const float4*)(g_eout + (size_t)s0 * NH + h);
    float4 b = *(const float4*)(g_eout + (size_t)s1 * NH + h);
    o.x += p0 * a.x + p1 * b.x;
    o.y += p0 * a.y + p1 * b.y;
    o.z += p0 * a.z + p1 * b.z;
    o.w += p0 * a.w + p1 * b.w;
    *(float4*)(out + (size_t)t * NH + h) = o;
}

// ---------------- launch ----------------
extern "C" void kernel_launch(void* const* d_in, const int* in_sizes, int n_in,
                              void* d_out, int out_size) {
    const float* x    = (const float*)d_in[0];
    const float* gw   = (const float*)d_in[1];
    const float* beta = (const float*)d_in[2];
    const float* gpw  = (const float*)d_in[3];
    const float* upw  = (const float*)d_in[4];
    const float* dpw  = (const float*)d_in[5];
    const float* sgw  = (const float*)d_in[6];
    const float* suw  = (const float*)d_in[7];
    const float* sdw  = (const float*)d_in[8];
    float* out = (float*)d_out;

    cudaFuncSetAttribute(moe_gemm1_mma<false>, cudaFuncAttributeMaxDynamicSharedMemorySize, SMEM1_BYTES);
    cudaFuncSetAttribute(moe_gemm1_mma<true>,  cudaFuncAttributeMaxDynamicSharedMemorySize, SMEM1_BYTES);
    cudaFuncSetAttribute(moe_gemm2_mma<false>, cudaFuncAttributeMaxDynamicSharedMemorySize, SMEM2_BYTES);
    cudaFuncSetAttribute(moe_gemm2_mma<true>,  cudaFuncAttributeMaxDynamicSharedMemorySize, SMEM2_BYTES);

    moe_route<<<NTOK, 256>>>(x, gw, beta);
    moe_build<<<1, 512>>>();

    moe_gemm1_mma<false><<<dim3(NM / 128, 40), 512, SMEM1_BYTES>>>(x, gpw, upw);
    moe_gemm1_mma<true> <<<dim3(NM / 128, NTOK / 128), 512, SMEM1_BYTES>>>(x, sgw, suw);

    moe_gemm2_mma<true> <<<dim3(NH / 128, NTOK / 128), 512, SMEM2_BYTES>>>(sdw, out);
    moe_gemm2_mma<false><<<dim3(NH / 128, 40), 512, SMEM2_BYTES>>>(dpw, out);

    moe_combine<<<NTOK, 256>>>(out);
}